// round 1
// baseline (speedup 1.0000x reference)
#include <cuda_runtime.h>
#include <cstdint>

// MeanCellExtrator: per-(image,label) mean of 16-channel pred/target over
// pixels sharing a nucleus label (1..512), label 0 = background.
//
// Output buffer layout (f32, 67584 elems):
//   [0      , 32768)  pred_means  [B*512, 16]
//   [32768  , 65536)  target_means[B*512, 16]
//   [65536  , 67584)  cell_ids    [B*512]   (numeric float: label or 0)
//
// Strategy: atomic-free smem accumulation.
//   - 296 CTAs (74 strips x 4 images), 256 threads, 2 CTAs/SM.
//   - smem: accP[513][20], accT[513][20], cnt[513]  (rows padded to 20 floats
//     so label*80B hits all 8 LDS bank-groups -> ~2.5x conflict, not 8x).
//   - warp w owns 4 channel-slots exclusively (0-3: pred, 4-7: target)
//     => no cross-warp races on accumulators; warp 0 also owns counts.
//   - intra-warp label collisions folded into group leader via
//     __match_any_sync + convergent shuffle loop, then one LDS.128/STS.128 RMW.
//   - global merge via scalar atomicAdd into d_out (small), finalize divides.

#define FULLMASK 0xffffffffu

constexpr int C      = 16;
constexpr int HW     = 1 << 20;     // 1024*1024
constexpr int NLAB   = 512;
constexpr int ROWW   = 20;          // padded row stride (floats)
constexpr int STRIPS = 74;          // 74 * 4 images = 296 CTAs = 2/SM
constexpr int NGROUP = HW / 128;    // 8192 groups of 128 pixels per image

constexpr int ROWS        = NLAB + 1;                   // index by label directly
constexpr int SMEM_FLOATS = ROWS * ROWW * 2 + ROWS;     // 21033 floats = 84132 B

__global__ __launch_bounds__(256) void zero_out_kernel(float* out, int n) {
    int i = blockIdx.x * blockDim.x + threadIdx.x;
    if (i < n) out[i] = 0.0f;
}

__global__ __launch_bounds__(256, 2)
void seg_accum_kernel(const float* __restrict__ pred,
                      const float* __restrict__ targ,
                      const int*   __restrict__ nuc,
                      float* __restrict__ out)
{
    extern __shared__ float sm[];
    float* accP = sm;                     // ROWS*ROWW
    float* accT = sm + ROWS * ROWW;       // ROWS*ROWW
    float* cnt  = sm + 2 * ROWS * ROWW;   // ROWS

    const int tid  = threadIdx.x;
    const int warp = tid >> 5;
    const int lane = tid & 31;
    const int b    = blockIdx.y;
    const int s    = blockIdx.x;

    // ---- zero smem accumulators (vectorized) ----
    {
        float4 z = make_float4(0.f, 0.f, 0.f, 0.f);
        int n4 = SMEM_FLOATS >> 2;
        float4* p4 = reinterpret_cast<float4*>(sm);
        for (int i = tid; i < n4; i += 256) p4[i] = z;
        for (int i = (n4 << 2) + tid; i < SMEM_FLOATS; i += 256) sm[i] = 0.f;
    }
    __syncthreads();

    const int  cgrp   = warp & 3;           // which 4-channel group
    const bool isPred = (warp < 4);
    const bool doCnt  = (warp == 0);
    const float* plane = (isPred ? pred : targ) + (size_t)(b * C + cgrp * 4) * HW;
    float* acc = isPred ? accP : accT;
    const int* lab = nuc + (size_t)b * HW;
    const int  w4  = cgrp * 4;

    const int g0 = (s * NGROUP) / STRIPS;
    const int g1 = ((s + 1) * NGROUP) / STRIPS;

    for (int g = g0; g < g1; ++g) {
        const int base = (g << 7) + (lane << 2);   // 128 px / warp-iter, 4 / lane
        int4   L  = __ldg(reinterpret_cast<const int4*>(lab + base));
        float4 V0 = __ldg(reinterpret_cast<const float4*>(plane + base));
        float4 V1 = __ldg(reinterpret_cast<const float4*>(plane + HW + base));
        float4 V2 = __ldg(reinterpret_cast<const float4*>(plane + 2 * (size_t)HW + base));
        float4 V3 = __ldg(reinterpret_cast<const float4*>(plane + 3 * (size_t)HW + base));

        const int   lv[4]  = {L.x, L.y, L.z, L.w};
        const float c0[4]  = {V0.x, V0.y, V0.z, V0.w};
        const float c1[4]  = {V1.x, V1.y, V1.z, V1.w};
        const float c2[4]  = {V2.x, V2.y, V2.z, V2.w};
        const float c3[4]  = {V3.x, V3.y, V3.z, V3.w};

        #pragma unroll
        for (int j = 0; j < 4; ++j) {
            int   label = lv[j];
            float v0 = c0[j], v1 = c1[j], v2 = c2[j], v3 = c3[j];

            const bool act = ((unsigned)(label - 1)) < (unsigned)NLAB;
            const unsigned key = act ? (unsigned)label : (0x8000u | lane);
            const unsigned grp = __match_any_sync(FULLMASK, key);
            const int  leader   = __ffs(grp) - 1;
            const bool isLeader = act && (lane == leader);

            // fold duplicate lanes into the leader (convergent; usually 0-1 rounds)
            unsigned rem = grp & (grp - 1);
            while (__ballot_sync(FULLMASK, rem)) {
                const int src = rem ? (__ffs(rem) - 1) : lane;
                float a0 = __shfl_sync(FULLMASK, v0, src);
                float a1 = __shfl_sync(FULLMASK, v1, src);
                float a2 = __shfl_sync(FULLMASK, v2, src);
                float a3 = __shfl_sync(FULLMASK, v3, src);
                if (isLeader && rem) { v0 += a0; v1 += a1; v2 += a2; v3 += a3; }
                rem &= rem - 1;
            }

            if (isLeader) {
                float* p = acc + label * ROWW + w4;          // 16B aligned
                float4 o = *reinterpret_cast<float4*>(p);
                o.x += v0; o.y += v1; o.z += v2; o.w += v3;
                *reinterpret_cast<float4*>(p) = o;
                if (doCnt) cnt[label] += (float)__popc(grp);
            }
        }
    }
    __syncthreads();

    // ---- merge this CTA's partials into global sums (d_out) ----
    for (int r = tid; r < NLAB; r += 256) {
        const int   L = r + 1;
        const float c = cnt[L];
        if (c != 0.f) {
            const int gi = b * NLAB + r;
            float* po = out + (size_t)gi * C;
            float* to = out + 32768 + (size_t)gi * C;
            #pragma unroll
            for (int k = 0; k < C; ++k) {
                atomicAdd(po + k, accP[L * ROWW + k]);
                atomicAdd(to + k, accT[L * ROWW + k]);
            }
            atomicAdd(out + 65536 + gi, c);
        }
    }
}

__global__ __launch_bounds__(256) void finalize_kernel(float* out) {
    int i = blockIdx.x * blockDim.x + threadIdx.x;
    if (i >= 4 * NLAB) return;
    const float c = out[65536 + i];
    const float d = fmaxf(c, 1.0f);
    #pragma unroll
    for (int k = 0; k < C; ++k) {
        out[(size_t)i * C + k]          /= d;
        out[32768 + (size_t)i * C + k]  /= d;
    }
    out[65536 + i] = (c > 0.f) ? (float)((i & (NLAB - 1)) + 1) : 0.f;
}

extern "C" void kernel_launch(void* const* d_in, const int* in_sizes, int n_in,
                              void* d_out, int out_size)
{
    const float* pred = (const float*)d_in[0];
    const float* targ = (const float*)d_in[1];
    const int*   nuc  = (const int*)d_in[2];
    float* out = (float*)d_out;

    const int B = in_sizes[2] / HW;   // 4

    const int smemB = SMEM_FLOATS * (int)sizeof(float);
    cudaFuncSetAttribute(seg_accum_kernel,
                         cudaFuncAttributeMaxDynamicSharedMemorySize, smemB);

    zero_out_kernel<<<(out_size + 255) / 256, 256>>>(out, out_size);
    dim3 grid(STRIPS, B);
    seg_accum_kernel<<<grid, 256, smemB>>>(pred, targ, nuc, out);
    finalize_kernel<<<(B * NLAB + 255) / 256, 256>>>(out);
}